// round 16
// baseline (speedup 1.0000x reference)
#include <cuda_runtime.h>
#include <cstdint>

#define NEN   64368
#define NREL  12
#define DIM   128
#define NB    8
#define NITEM 6924
#define NE    1000000
#define BATCH 128
#define SEQL  32

#define SB    1024                       // scan block size
#define NBLK  ((NEN + SB - 1) / SB)      // 63 scan blocks
#define NEEDW ((NEN + 31) / 32)          // 2012 bitmask words (8 KB)

// ---------------- scratch (no cudaMalloc allowed) ----------------
__device__ __align__(16) float g_aggr[(size_t)NEN * DIM];   // only live rows touched
__device__ __align__(16) float g_u[BATCH * DIM];
__device__ unsigned g_needbm[NEEDW];  // live-node bitmask (L1-resident)
__device__ int g_scnt[NEN];       // per-src filtered out-degree
__device__ int g_deg[NEN];        // per-dst filtered in-degree
__device__ int g_off[NEN + 1];    // CSR offsets by src (filtered edges)
__device__ int g_cur[NEN];        // scatter cursors
__device__ int g_sorted[NE];      // packed (type<<16)|dst, grouped by src
__device__ int g_bflag[NBLK];     // decoupled-lookback: 0=invalid 1=agg 2=prefix
__device__ int g_bagg[NBLK];
__device__ int g_bpref[NBLK];

__device__ __forceinline__ bool is_live(int n) {
    return (__ldg(g_needbm + (n >> 5)) >> (n & 31)) & 1u;
}

// ---------------- phase 0: init bitmask/counters/flags + zero item aggr rows -----
__global__ void k_prep() {
    int i = blockIdx.x * blockDim.x + threadIdx.x;
    if (i < NEN) { g_scnt[i] = 0; g_deg[i] = 0; }
    if (i < NEEDW) {
        int base = i << 5;
        unsigned w;
        if (base + 32 <= NITEM)      w = 0xFFFFFFFFu;
        else if (base >= NITEM)      w = 0u;
        else                         w = (1u << (NITEM - base)) - 1u;
        g_needbm[i] = w;
    }
    if (i < NBLK) g_bflag[i] = 0;
    if (i < NITEM * (DIM / 4))
        ((float4*)g_aggr)[i] = make_float4(0.f, 0.f, 0.f, 0.f);
}

// ---------------- phase 1: mark seed rows >= NITEM, zero their aggr --------------
__global__ void k_mark(const int* __restrict__ seed_ids) {
    int i = blockIdx.x * blockDim.x + threadIdx.x;
    if (i >= BATCH * SEQL) return;
    int id = __ldg(seed_ids + i);
    if (id >= NITEM && id < NEN) {
        unsigned bit = 1u << (id & 31);
        if ((atomicOr(&g_needbm[id >> 5], bit) & bit) == 0u) {
            float4* row = (float4*)(g_aggr + (size_t)id * DIM);
            for (int j = 0; j < DIM / 4; j++) row[j] = make_float4(0.f, 0.f, 0.f, 0.f);
        }
    }
}

// ---------------- phase 2: filtered histograms (4 edges/thread, bitmask) ---------
__global__ void k_hist(const int* __restrict__ ei) {
    int t = blockIdx.x * blockDim.x + threadIdx.x;
    if (t >= NE / 4) return;
    int4 s4 = __ldg((const int4*)ei + t);
    int4 d4 = __ldg((const int4*)(ei + NE) + t);
    if (is_live(d4.x)) { atomicAdd(&g_scnt[s4.x], 1); atomicAdd(&g_deg[d4.x], 1); }
    if (is_live(d4.y)) { atomicAdd(&g_scnt[s4.y], 1); atomicAdd(&g_deg[d4.y], 1); }
    if (is_live(d4.z)) { atomicAdd(&g_scnt[s4.z], 1); atomicAdd(&g_deg[d4.z], 1); }
    if (is_live(d4.w)) { atomicAdd(&g_scnt[s4.w], 1); atomicAdd(&g_deg[d4.w], 1); }
}

// ---------------- phase 3: single-pass scan (decoupled lookback, 63 blocks) ------
__global__ void k_scan() {
    __shared__ int s[SB];
    __shared__ int s_excl;
    int t   = threadIdx.x;
    int bid = blockIdx.x;
    int g   = bid * SB + t;
    int v   = (g < NEN) ? g_scnt[g] : 0;
    s[t] = v;
    __syncthreads();
#pragma unroll
    for (int o = 1; o < SB; o <<= 1) {
        int x = (t >= o) ? s[t - o] : 0;
        __syncthreads();
        s[t] += x;
        __syncthreads();
    }
    int agg = s[SB - 1];   // block total (all threads see it)

    if (t == 0) {
        int excl = 0;
        if (bid == 0) {
            g_bpref[0] = agg;
            __threadfence();
            atomicExch(&g_bflag[0], 2);
        } else {
            g_bagg[bid] = agg;
            __threadfence();
            atomicExch(&g_bflag[bid], 1);
            int j = bid - 1;
            while (j >= 0) {
                int f;
                do { f = atomicAdd(&g_bflag[j], 0); } while (f == 0);
                if (f == 2) { excl += atomicAdd(&g_bpref[j], 0); break; }
                excl += atomicAdd(&g_bagg[j], 0);
                j--;
            }
            g_bpref[bid] = excl + agg;
            __threadfence();
            atomicExch(&g_bflag[bid], 2);
        }
        s_excl = excl;
    }
    __syncthreads();

    if (g < NEN) {
        int off = s_excl + s[t] - v;   // global exclusive prefix
        g_off[g] = off;
        g_cur[g] = off;
        if (g == NEN - 1) g_off[NEN] = off + v;
    }
}

// ---------------- phase 4: filtered scatter, grouped by src (bitmask) ------------
__global__ void k_scatter(const int* __restrict__ ei, const int* __restrict__ et) {
    int t = blockIdx.x * blockDim.x + threadIdx.x;
    if (t >= NE / 4) return;
    int4 s4 = __ldg((const int4*)ei + t);
    int4 d4 = __ldg((const int4*)(ei + NE) + t);
    int4 t4 = __ldg((const int4*)et + t);
    int p;
    if (is_live(d4.x)) { p = atomicAdd(&g_cur[s4.x], 1); g_sorted[p] = (t4.x << 16) | d4.x; }
    if (is_live(d4.y)) { p = atomicAdd(&g_cur[s4.y], 1); g_sorted[p] = (t4.y << 16) | d4.y; }
    if (is_live(d4.z)) { p = atomicAdd(&g_cur[s4.z], 1); g_sorted[p] = (t4.z << 16) | d4.z; }
    if (is_live(d4.w)) { p = atomicAdd(&g_cur[s4.w], 1); g_sorted[p] = (t4.w << 16) | d4.w; }
}

// ---------------- phase 5: fused msg-compute + scatter-add (1 warp per src) ------
__global__ void k_gather(const float* __restrict__ basis, const float* __restrict__ att) {
    __shared__ float s_att[NREL * NB];
    int tid = threadIdx.x;
    if (tid < NREL * NB) s_att[tid] = att[tid];
    __syncthreads();

    int src  = (blockIdx.x * blockDim.x + tid) >> 5;
    int lane = tid & 31;
    if (src >= NEN) return;

    int beg = __ldg(g_off + src);
    int end = __ldg(g_off + src + 1);
    if (beg == end) return;

    const float4* b4 = (const float4*)basis;
    float4 bb[NB];
#pragma unroll
    for (int b = 0; b < NB; b++)
        bb[b] = __ldg(b4 + ((size_t)b * NEN + src) * (DIM / 4) + lane);

    int k = beg;
    for (; k + 1 < end; k += 2) {
        int p0 = __ldg(g_sorted + k);
        int p1 = __ldg(g_sorted + k + 1);
        int t0 = p0 >> 16, d0 = p0 & 0xFFFF;
        int t1 = p1 >> 16, d1 = p1 & 0xFFFF;
        float4 m0 = make_float4(0.f, 0.f, 0.f, 0.f);
        float4 m1 = make_float4(0.f, 0.f, 0.f, 0.f);
#pragma unroll
        for (int b = 0; b < NB; b++) {
            float c0 = s_att[t0 * NB + b];
            float c1 = s_att[t1 * NB + b];
            m0.x += c0 * bb[b].x; m0.y += c0 * bb[b].y;
            m0.z += c0 * bb[b].z; m0.w += c0 * bb[b].w;
            m1.x += c1 * bb[b].x; m1.y += c1 * bb[b].y;
            m1.z += c1 * bb[b].z; m1.w += c1 * bb[b].w;
        }
        float* a0 = g_aggr + (size_t)d0 * DIM + lane * 4;
        float* a1 = g_aggr + (size_t)d1 * DIM + lane * 4;
        asm volatile("red.global.add.v4.f32 [%0], {%1,%2,%3,%4};"
                     :: "l"(a0), "f"(m0.x), "f"(m0.y), "f"(m0.z), "f"(m0.w) : "memory");
        asm volatile("red.global.add.v4.f32 [%0], {%1,%2,%3,%4};"
                     :: "l"(a1), "f"(m1.x), "f"(m1.y), "f"(m1.z), "f"(m1.w) : "memory");
    }
    if (k < end) {
        int p0 = __ldg(g_sorted + k);
        int t0 = p0 >> 16, d0 = p0 & 0xFFFF;
        float4 m0 = make_float4(0.f, 0.f, 0.f, 0.f);
#pragma unroll
        for (int b = 0; b < NB; b++) {
            float c0 = s_att[t0 * NB + b];
            m0.x += c0 * bb[b].x; m0.y += c0 * bb[b].y;
            m0.z += c0 * bb[b].z; m0.w += c0 * bb[b].w;
        }
        float* a0 = g_aggr + (size_t)d0 * DIM + lane * 4;
        asm volatile("red.global.add.v4.f32 [%0], {%1,%2,%3,%4};"
                     :: "l"(a0), "f"(m0.x), "f"(m0.y), "f"(m0.z), "f"(m0.w) : "memory");
    }
}

// ---------------- phase 6: attention pooling, finalize inline --------------------
__global__ void k_pool(const int* __restrict__ seed_ids, const int* __restrict__ seed_len,
                       const float* __restrict__ A, const float* __restrict__ bvec,
                       const float* __restrict__ root, const float* __restrict__ bias) {
    __shared__ float sh_h[SEQL][DIM];
    __shared__ float sh_t[SEQL][DIM + 1];
    __shared__ float sh_e[SEQL];
    __shared__ float sh_attn[SEQL];
    __shared__ int   sid[SEQL];
    __shared__ float sinv[SEQL];

    int b = blockIdx.x;
    int j = threadIdx.x;
    int len = __ldg(seed_len + b);

    if (j < SEQL) {
        int id = __ldg(seed_ids + b * SEQL + j);
        sid[j]  = id;
        sinv[j] = 1.f / fmaxf((float)__ldg(g_deg + id), 1.f);
    }
    __syncthreads();

    float bsj = __ldg(bias + j);
#pragma unroll
    for (int l = 0; l < SEQL; l++) {
        size_t o = (size_t)sid[l] * DIM + j;
        sh_h[l][j] = g_aggr[o] * sinv[l] + __ldg(root + o) + bsj;   // finalize inline
    }
    __syncthreads();

    float pe[SEQL];
#pragma unroll
    for (int l = 0; l < SEQL; l++) pe[l] = 0.f;
    for (int d = 0; d < DIM; d++) {
        float a = __ldg(A + d * DIM + j);
#pragma unroll
        for (int l = 0; l < SEQL; l++) pe[l] += sh_h[l][d] * a;
    }
    float bv = __ldg(bvec + j);
#pragma unroll
    for (int l = 0; l < SEQL; l++) sh_t[l][j] = tanhf(pe[l]) * bv;
    __syncthreads();

    if (j < SEQL) {
        float s = 0.f;
        for (int d = 0; d < DIM; d++) s += sh_t[j][d];
        sh_e[j] = s;
    }
    __syncthreads();

    if (j < 32) {
        float val = (j < len) ? sh_e[j] : -1e30f;
        float m = val;
#pragma unroll
        for (int o = 16; o; o >>= 1) m = fmaxf(m, __shfl_xor_sync(0xffffffffu, m, o));
        float ex = (j < len) ? expf(val - m) : 0.f;
        float s = ex;
#pragma unroll
        for (int o = 16; o; o >>= 1) s += __shfl_xor_sync(0xffffffffu, s, o);
        sh_attn[j] = (len > 0) ? ex / s : 0.f;
    }
    __syncthreads();

    float u = 0.f;
#pragma unroll
    for (int l = 0; l < SEQL; l++) u += sh_attn[l] * sh_h[l][j];
    g_u[b * DIM + j] = u;
}

// ---------------- phase 7: scores = u @ items.T + out_bias, finalize inline ------
#define ITEMS 32
__global__ void k_score(const float* __restrict__ out_bias, float* __restrict__ out,
                        const float* __restrict__ root, const float* __restrict__ bias) {
    __shared__ float shn[ITEMS * DIM];
    __shared__ float shout[ITEMS][BATCH + 1];
    __shared__ float sinv[ITEMS];

    int tid = threadIdx.x;
    int i0  = blockIdx.x * ITEMS;

    if (tid < ITEMS) {
        int item = i0 + tid;
        sinv[tid] = (item < NITEM)
                  ? 1.f / fmaxf((float)__ldg(g_deg + item), 1.f) : 0.f;
    }
    __syncthreads();

    for (int idx = tid; idx < ITEMS * DIM; idx += BATCH) {
        int it = idx >> 7, d = idx & 127;
        int item = i0 + it;
        float v = 0.f;
        if (item < NITEM) {
            size_t o = (size_t)item * DIM + d;
            v = g_aggr[o] * sinv[it] + __ldg(root + o) + __ldg(bias + d);
        }
        shn[idx] = v;
    }
    __syncthreads();

    float acc[ITEMS];
#pragma unroll
    for (int it = 0; it < ITEMS; it++) acc[it] = 0.f;

    const float4* u4   = (const float4*)(g_u + tid * DIM);
    const float4* shn4 = (const float4*)shn;
#pragma unroll 4
    for (int d4 = 0; d4 < DIM / 4; d4++) {
        float4 uv = u4[d4];
#pragma unroll
        for (int it = 0; it < ITEMS; it++) {
            float4 nv = shn4[it * (DIM / 4) + d4];
            acc[it] += uv.x * nv.x + uv.y * nv.y + uv.z * nv.z + uv.w * nv.w;
        }
    }

#pragma unroll
    for (int it = 0; it < ITEMS; it++) shout[it][tid] = acc[it];
    __syncthreads();

    for (int idx = tid; idx < BATCH * ITEMS; idx += BATCH) {
        int bb = idx >> 5, it = idx & 31;
        int item = i0 + it;
        if (item < NITEM)
            out[(size_t)bb * NITEM + item] = shout[it][bb] + __ldg(out_bias + item);
    }
}

// ---------------- launch (single stream — graph-capture safe) --------------------
extern "C" void kernel_launch(void* const* d_in, const int* in_sizes, int n_in,
                              void* d_out, int out_size) {
    const int*   edge_idx  = (const int*)d_in[0];
    const int*   edge_type = (const int*)d_in[1];
    const int*   seed_ids  = (const int*)d_in[2];
    const int*   seed_len  = (const int*)d_in[3];
    const float* basis     = (const float*)d_in[5];
    const float* att       = (const float*)d_in[6];
    const float* root      = (const float*)d_in[7];
    const float* rgcn_bias = (const float*)d_in[8];
    const float* attn_a    = (const float*)d_in[9];
    const float* attn_b    = (const float*)d_in[10];
    const float* out_bias  = (const float*)d_in[11];
    float* out = (float*)d_out;

    int prep_n = NITEM * (DIM / 4) > NEN ? NITEM * (DIM / 4) : NEN;
    k_prep   <<<(prep_n + 255) / 256, 256>>>();
    k_mark   <<<(BATCH * SEQL + 255) / 256, 256>>>(seed_ids);
    k_hist   <<<(NE / 4 + 255) / 256, 256>>>(edge_idx);
    k_scan   <<<NBLK, SB>>>();
    k_scatter<<<(NE / 4 + 255) / 256, 256>>>(edge_idx, edge_type);
    k_gather <<<(NEN * 32 + 255) / 256, 256>>>(basis, att);
    k_pool   <<<BATCH, DIM>>>(seed_ids, seed_len, attn_a, attn_b, root, rgcn_bias);
    k_score  <<<(NITEM + ITEMS - 1) / ITEMS, BATCH>>>(out_bias, out, root, rgcn_bias);
}